// round 14
// baseline (speedup 1.0000x reference)
#include <cuda_runtime.h>
#include <cuda_bf16.h>
#include <cuda_fp16.h>
#include <cstdint>

#define N_NODES   100000
#define N_EDGES   3200000
#define N_FEAT    128
#define HIDDEN    16
#define N_CLASSES 10
#define N_GRAPHS  512

#define SCAN_B 1024
#define NBLK   ((N_NODES + SCAN_B - 1) / SCAN_B)   // 98

// ---------------- scratch (static __device__; no allocation) ----------------
__device__ __align__(16)  int    g_csr[N_EDGES];        // src only (4B/edge)
__device__ __align__(16)  int    g_pos[N_EDGES];        // slot within dst bucket
__device__ __align__(16)  int    g_off[N_NODES + 1];
__device__ __align__(16)  int    g_cnt[N_NODES];        // self-cleaned by k_scan
__device__ __align__(16)  unsigned long long g_look[NBLK];  // reset by k_head
__device__ __align__(16)  float  g_dinv[N_NODES];
__device__ __align__(128) __half g_hh[2][N_NODES * HIDDEN];  // hs = dinv*h, fp16
__device__ __align__(16)  float  g_pooled[N_GRAPHS * HIDDEN]; // reset by k_head

// ---------------- helpers ----------------
__device__ __forceinline__ void red_add_v4(float4* addr, float4 v) {
    asm volatile("red.global.add.v4.f32 [%0], {%1,%2,%3,%4};"
                 :: "l"(addr), "f"(v.x), "f"(v.y), "f"(v.z), "f"(v.w)
                 : "memory");
}

// int64 iff the high 32-bit words of the first 4 entries are all zero
__device__ __forceinline__ int detect64(const int* __restrict__ ei32) {
    return (ei32[1] | ei32[3] | ei32[5] | ei32[7]) == 0;
}

__device__ __forceinline__ uint2 pack4(float a, float b, float c, float d) {
    __half2 lo = __floats2half2_rn(a, b), hi = __floats2half2_rn(c, d);
    uint2 r;
    r.x = *(unsigned*)&lo; r.y = *(unsigned*)&hi;
    return r;
}

__device__ __forceinline__ float4 unpack4(uint2 u) {
    __half2 lo = *(__half2*)&u.x, hi = *(__half2*)&u.y;
    float2 f0 = __half22float2(lo), f1 = __half22float2(hi);
    return make_float4(f0.x, f0.y, f1.x, f1.y);
}

// load 8 edge indices (src half_off=0 or dst half_off=N_EDGES) at base t*8
__device__ __forceinline__ void load8(const void* p, long long half_off, int t,
                                      int is64, int* v) {
    if (!is64) {
        const int4* q = (const int4*)((const int*)p + half_off);
        int4 a = q[t * 2], b = q[t * 2 + 1];
        v[0] = a.x; v[1] = a.y; v[2] = a.z; v[3] = a.w;
        v[4] = b.x; v[5] = b.y; v[6] = b.z; v[7] = b.w;
    } else {
        const long long* q = (const long long*)p + half_off;
#pragma unroll
        for (int k = 0; k < 8; k++) v[k] = (int)q[(long long)t * 8 + k];
    }
}

// ---------------- preprocessing ----------------

// count in-degree AND record each edge's slot in its dst bucket.
// Runs ALONE (no gemm1 contention). 8 edges/thread; pos store is coalesced.
__global__ void k_count(const void* __restrict__ ei) {
    int is64 = detect64((const int*)ei);
    int t = blockIdx.x * blockDim.x + threadIdx.x;
    if (t * 8 >= N_EDGES) return;
    int dd[8];
    load8(ei, N_EDGES, t, is64, dd);
#pragma unroll
    for (int k = 0; k < 8; k++)
        if ((unsigned)dd[k] >= N_NODES) dd[k] = 0;
    int pp[8];
#pragma unroll
    for (int k = 0; k < 8; k++)
        pp[k] = atomicAdd(&g_cnt[dd[k]], 1);
    int4* po = (int4*)g_pos;
    po[t * 2]     = make_int4(pp[0], pp[1], pp[2], pp[3]);
    po[t * 2 + 1] = make_int4(pp[4], pp[5], pp[6], pp[7]);
}

// single-launch exclusive scan (decoupled lookback) + dinv; self-cleans g_cnt
__global__ void k_scan() {
    __shared__ int sh[SCAN_B];
    __shared__ int s_pfx;
    int j = blockIdx.x;
    int i = j * SCAN_B + threadIdx.x;
    int v = (i < N_NODES) ? g_cnt[i] : 0;
    if (i < N_NODES) {
        g_dinv[i] = rsqrtf((float)(v + 1));
        g_cnt[i] = 0;                        // self-clean for next replay
    }
    sh[threadIdx.x] = v;
    __syncthreads();
#pragma unroll
    for (int off = 1; off < SCAN_B; off <<= 1) {
        int t = (threadIdx.x >= off) ? sh[threadIdx.x - off] : 0;
        __syncthreads();
        sh[threadIdx.x] += t;
        __syncthreads();
    }
    unsigned total = (unsigned)sh[SCAN_B - 1];
    if (threadIdx.x == 0)
        atomicExch(&g_look[j], (1ull << 32) | total);   // publish aggregate
    if (threadIdx.x < 32) {
        int lane = threadIdx.x;
        unsigned prefix = 0;
        int k = j - 1;
        if (j == 0 && lane == 0) s_pfx = 0;
        while (k >= 0) {
            int idx = k - lane;
            unsigned st = 1, val = 0;
            if (idx >= 0) {
                unsigned long long w;
                do { w = atomicOr(&g_look[idx], 0ull); st = (unsigned)(w >> 32); }
                while (st == 0);
                val = (unsigned)w;
            }
            unsigned ball = __ballot_sync(0xffffffffu, st == 2 && idx >= 0);
            if (ball) {
                int p = __ffs(ball) - 1;
                unsigned contrib = (lane <= p) ? val : 0;
#pragma unroll
                for (int o = 16; o; o >>= 1)
                    contrib += __shfl_down_sync(0xffffffffu, contrib, o);
                prefix += contrib;
                break;
            } else {
                unsigned contrib = (idx >= 0) ? val : 0;
#pragma unroll
                for (int o = 16; o; o >>= 1)
                    contrib += __shfl_down_sync(0xffffffffu, contrib, o);
                prefix += contrib;
                k -= 32;
            }
        }
        if (lane == 0 && j > 0) {
            atomicExch(&g_look[j], (2ull << 32) | (prefix + total));
            s_pfx = (int)prefix;
        }
        if (lane == 0 && j == 0)
            atomicExch(&g_look[0], (2ull << 32) | total);
    }
    __syncthreads();
    int pfx = s_pfx;
    if (i < N_NODES)
        g_off[i] = sh[threadIdx.x] - v + pfx;   // exclusive + block prefix
    if (i == 0) g_off[N_NODES] = N_EDGES;
}

// scatter src ids into CSR — NO atomics: csr[off[dst]+pos[e]] = src.
// Latency-bound; overlaps gemm1+scale on the side stream.
__global__ void k_fill(const void* __restrict__ ei) {
    int is64 = detect64((const int*)ei);
    int t = blockIdx.x * blockDim.x + threadIdx.x;
    if (t * 8 >= N_EDGES) return;
    int ss[8], dd[8];
    load8(ei, 0, t, is64, ss);
    load8(ei, N_EDGES, t, is64, dd);
    const int4* po = (const int4*)g_pos;
    int4 pa = po[t * 2], pb = po[t * 2 + 1];
    int pp[8] = { pa.x, pa.y, pa.z, pa.w, pb.x, pb.y, pb.z, pb.w };
#pragma unroll
    for (int k = 0; k < 8; k++) {
        if ((unsigned)ss[k] >= N_NODES) ss[k] = 0;
        if ((unsigned)dd[k] >= N_NODES) dd[k] = 0;
    }
    int oo[8];
#pragma unroll
    for (int k = 0; k < 8; k++) oo[k] = g_off[dd[k]];   // 8 independent gathers
#pragma unroll
    for (int k = 0; k < 8; k++) g_csr[oo[k] + pp[k]] = ss[k];
}

// ---------------- compute ----------------

// h0 = x @ W1 (UNSCALED, fp16 store). One thread per node. Forked after scan.
__global__ void k_gemm1(const float* __restrict__ x, const float* __restrict__ W1) {
    __shared__ float Ws[N_FEAT * HIDDEN];
    for (int i = threadIdx.x; i < N_FEAT * HIDDEN; i += blockDim.x) Ws[i] = W1[i];
    __syncthreads();
    int n = blockIdx.x * blockDim.x + threadIdx.x;
    if (n >= N_NODES) return;
    const float4* xr = (const float4*)(x + (size_t)n * N_FEAT);
    const float4* W4 = (const float4*)Ws;
    float4 a0 = make_float4(0.f, 0.f, 0.f, 0.f), a1 = a0, a2 = a0, a3 = a0;
#pragma unroll 4
    for (int k4 = 0; k4 < N_FEAT / 4; k4++) {
        float4 v = xr[k4];
#pragma unroll
        for (int c = 0; c < 4; c++) {
            float xk = (c == 0) ? v.x : (c == 1) ? v.y : (c == 2) ? v.z : v.w;
            int row = (k4 * 4 + c) * 4;
            float4 w0 = W4[row + 0], w1 = W4[row + 1], w2 = W4[row + 2], w3 = W4[row + 3];
            a0.x += xk * w0.x; a0.y += xk * w0.y; a0.z += xk * w0.z; a0.w += xk * w0.w;
            a1.x += xk * w1.x; a1.y += xk * w1.y; a1.z += xk * w1.z; a1.w += xk * w1.w;
            a2.x += xk * w2.x; a2.y += xk * w2.y; a2.z += xk * w2.z; a2.w += xk * w2.w;
            a3.x += xk * w3.x; a3.y += xk * w3.y; a3.z += xk * w3.z; a3.w += xk * w3.w;
        }
    }
    uint2 u0 = pack4(a0.x, a0.y, a0.z, a0.w);
    uint2 u1 = pack4(a1.x, a1.y, a1.z, a1.w);
    uint2 u2 = pack4(a2.x, a2.y, a2.z, a2.w);
    uint2 u3 = pack4(a3.x, a3.y, a3.z, a3.w);
    uint4* ho = (uint4*)&g_hh[0][n * N_FEAT / 8];   // == n*HIDDEN
    ho = (uint4*)&g_hh[0][n * HIDDEN];
    ho[0] = make_uint4(u0.x, u0.y, u1.x, u1.y);
    ho[1] = make_uint4(u2.x, u2.y, u3.x, u3.y);
}

// hs0 = dinv * h0 in place (after gemm1; dinv ready since scan). Side stream.
__global__ void k_scale() {
    int n = blockIdx.x * blockDim.x + threadIdx.x;
    if (n >= N_NODES) return;
    float di = g_dinv[n];
    uint4* p = (uint4*)&g_hh[0][n * HIDDEN];
    uint4 a = p[0], b = p[1];
    float4 f0 = unpack4(make_uint2(a.x, a.y));
    float4 f1 = unpack4(make_uint2(a.z, a.w));
    float4 f2 = unpack4(make_uint2(b.x, b.y));
    float4 f3 = unpack4(make_uint2(b.z, b.w));
    uint2 u0 = pack4(di * f0.x, di * f0.y, di * f0.z, di * f0.w);
    uint2 u1 = pack4(di * f1.x, di * f1.y, di * f1.z, di * f1.w);
    uint2 u2 = pack4(di * f2.x, di * f2.y, di * f2.z, di * f2.w);
    uint2 u3 = pack4(di * f3.x, di * f3.y, di * f3.z, di * f3.w);
    p[0] = make_uint4(u0.x, u0.y, u1.x, u1.y);
    p[1] = make_uint4(u2.x, u2.y, u3.x, u3.y);
}

// sum of hs[src] over the bucket — pure adds, 8-wide batched for MLP
__device__ __forceinline__ float4 agg_edges(const uint2* __restrict__ h4,
                                            int q, int beg, int end, float4 acc) {
    int e = beg;
    for (; e + 8 <= end; e += 8) {
        int s0 = g_csr[e + 0], s1 = g_csr[e + 1], s2 = g_csr[e + 2], s3 = g_csr[e + 3];
        int s4 = g_csr[e + 4], s5 = g_csr[e + 5], s6 = g_csr[e + 6], s7 = g_csr[e + 7];
        uint2 v0 = h4[s0 * 4 + q], v1 = h4[s1 * 4 + q];
        uint2 v2 = h4[s2 * 4 + q], v3 = h4[s3 * 4 + q];
        uint2 v4 = h4[s4 * 4 + q], v5 = h4[s5 * 4 + q];
        uint2 v6 = h4[s6 * 4 + q], v7 = h4[s7 * 4 + q];
#define ACC(vi) { float4 f = unpack4(vi); \
        acc.x += f.x; acc.y += f.y; acc.z += f.z; acc.w += f.w; }
        ACC(v0) ACC(v1) ACC(v2) ACC(v3) ACC(v4) ACC(v5) ACC(v6) ACC(v7)
    }
    for (; e < end; e++) {
        uint2 v = h4[g_csr[e] * 4 + q];
        ACC(v)
    }
#undef ACC
    return acc;
}

// Fused: agg = dinv*(hs[n]+Σhs[src]); t = relu(agg+b); hs_next = dinv*(t@W).
__global__ void k_agg_update(int cur, int nxt, const float* __restrict__ bias,
                             const float* __restrict__ Wn) {
    __shared__ float Ws[HIDDEN * HIDDEN];
    __shared__ float bs[HIDDEN];
    int t = threadIdx.x;
    if (t < HIDDEN * HIDDEN) Ws[t] = Wn[t];
    if (t < HIDDEN) bs[t] = bias[t];
    __syncthreads();
    int idx = blockIdx.x * blockDim.x + t;
    int n = idx >> 2, q = idx & 3;
    if (n >= N_NODES) return;               // whole-warp exit (400000 % 32 == 0)
    const uint2* h4 = (const uint2*)g_hh[cur];
    float4 acc = unpack4(h4[n * 4 + q]);    // self term = hs[n]
    acc = agg_edges(h4, q, g_off[n], g_off[n + 1], acc);
    float di = g_dinv[n];
    int gb = q * 4;
    float t0 = fmaxf(di * acc.x + bs[gb + 0], 0.f);
    float t1 = fmaxf(di * acc.y + bs[gb + 1], 0.f);
    float t2 = fmaxf(di * acc.z + bs[gb + 2], 0.f);
    float t3 = fmaxf(di * acc.w + bs[gb + 3], 0.f);
    float o0 = 0.f, o1 = 0.f, o2 = 0.f, o3 = 0.f;
#pragma unroll
    for (int r = 0; r < 4; r++) {
        float s0 = (r == 0) ? t0 : __shfl_xor_sync(0xffffffffu, t0, r);
        float s1 = (r == 0) ? t1 : __shfl_xor_sync(0xffffffffu, t1, r);
        float s2v = (r == 0) ? t2 : __shfl_xor_sync(0xffffffffu, t2, r);
        float s3 = (r == 0) ? t3 : __shfl_xor_sync(0xffffffffu, t3, r);
        int fb = (q ^ r) * 4;
        o0 += s0 * Ws[(fb + 0) * HIDDEN + gb + 0] + s1 * Ws[(fb + 1) * HIDDEN + gb + 0]
            + s2v * Ws[(fb + 2) * HIDDEN + gb + 0] + s3 * Ws[(fb + 3) * HIDDEN + gb + 0];
        o1 += s0 * Ws[(fb + 0) * HIDDEN + gb + 1] + s1 * Ws[(fb + 1) * HIDDEN + gb + 1]
            + s2v * Ws[(fb + 2) * HIDDEN + gb + 1] + s3 * Ws[(fb + 3) * HIDDEN + gb + 1];
        o2 += s0 * Ws[(fb + 0) * HIDDEN + gb + 2] + s1 * Ws[(fb + 1) * HIDDEN + gb + 2]
            + s2v * Ws[(fb + 2) * HIDDEN + gb + 2] + s3 * Ws[(fb + 3) * HIDDEN + gb + 2];
        o3 += s0 * Ws[(fb + 0) * HIDDEN + gb + 3] + s1 * Ws[(fb + 1) * HIDDEN + gb + 3]
            + s2v * Ws[(fb + 2) * HIDDEN + gb + 3] + s3 * Ws[(fb + 3) * HIDDEN + gb + 3];
    }
    ((uint2*)&g_hh[nxt][n * HIDDEN])[q] = pack4(di * o0, di * o1, di * o2, di * o3);
}

// Fused last layer: agg = dinv*(hs[n]+Σhs[src]) + b3; warp-segmented pool.
__global__ void k_agg_pool(int cur, const float* __restrict__ b3,
                           const void* __restrict__ batch,
                           const void* __restrict__ ei) {
    int is64 = detect64((const int*)ei);    // batch has same dtype as edge_index
    int idx = blockIdx.x * blockDim.x + threadIdx.x;
    int n = idx >> 2, q = idx & 3;
    if (n >= N_NODES) return;               // whole-warp exit
    int lane = threadIdx.x & 31;
    const uint2* h4 = (const uint2*)g_hh[cur];
    float4 acc = unpack4(h4[n * 4 + q]);
    acc = agg_edges(h4, q, g_off[n], g_off[n + 1], acc);
    float di = g_dinv[n];
    float4 bb = ((const float4*)b3)[q];
    acc.x = di * acc.x + bb.x; acc.y = di * acc.y + bb.y;
    acc.z = di * acc.z + bb.z; acc.w = di * acc.w + bb.w;
    int gph = is64 ? (int)((const long long*)batch)[n] : ((const int*)batch)[n];
#pragma unroll
    for (int s = 4; s < 32; s <<= 1) {
        float ox = __shfl_down_sync(0xffffffffu, acc.x, s);
        float oy = __shfl_down_sync(0xffffffffu, acc.y, s);
        float oz = __shfl_down_sync(0xffffffffu, acc.z, s);
        float ow = __shfl_down_sync(0xffffffffu, acc.w, s);
        int   og = __shfl_down_sync(0xffffffffu, gph, s);
        if (lane + s < 32 && og == gph) {
            acc.x += ox; acc.y += oy; acc.z += oz; acc.w += ow;
        }
    }
    int upg = __shfl_up_sync(0xffffffffu, gph, 4);
    bool leader = (lane < 4) || (upg != gph);
    if (leader && (unsigned)gph < N_GRAPHS)
        red_add_v4((float4*)&g_pooled[gph * HIDDEN + q * 4], acc);
}

// out[g][:] = pooled[g] @ Wlin + blin.  ONE 512-thread block (1 graph each).
// Self-cleans g_pooled and g_look for the next replay.
__global__ void k_head(const float* __restrict__ Wlin,
                       const float* __restrict__ blin, float* __restrict__ out) {
    int g = threadIdx.x;                     // 0..511
    float p[HIDDEN];
#pragma unroll
    for (int f = 0; f < HIDDEN; f++) p[f] = g_pooled[g * HIDDEN + f];
#pragma unroll
    for (int c = 0; c < N_CLASSES; c++) {
        float s = blin[c];
#pragma unroll
        for (int f = 0; f < HIDDEN; f++)
            s += p[f] * Wlin[f * N_CLASSES + c];
        out[g * N_CLASSES + c] = s;
    }
#pragma unroll
    for (int f = 0; f < HIDDEN; f++) g_pooled[g * HIDDEN + f] = 0.f;
    if (g < NBLK) g_look[g] = 0ull;
}

// ---------------- launch ----------------
extern "C" void kernel_launch(void* const* d_in, const int* in_sizes, int n_in,
                              void* d_out, int out_size) {
    const float* x     = (const float*)d_in[0];
    const void*  ei    = d_in[1];
    const void*  batch = d_in[2];
    const float* W1    = (const float*)d_in[3];
    const float* b1    = (const float*)d_in[4];
    const float* W2    = (const float*)d_in[5];
    const float* b2    = (const float*)d_in[6];
    const float* W3    = (const float*)d_in[7];
    const float* b3    = (const float*)d_in[8];
    const float* Wlin  = (const float*)d_in[9];
    const float* blin  = (const float*)d_in[10];
    float* out = (float*)d_out;

    static cudaStream_t s1 = nullptr;
    static cudaEvent_t  eScan = nullptr, e1 = nullptr;
    if (!s1) {
        cudaStreamCreateWithFlags(&s1, cudaStreamNonBlocking);
        cudaEventCreateWithFlags(&eScan, cudaEventDisableTiming);
        cudaEventCreateWithFlags(&e1, cudaEventDisableTiming);
    }

    const int T = 256;
    int gN  = (N_NODES + T - 1) / T;
    int gE8 = (N_EDGES / 8 + T - 1) / T;
    int gN4 = (N_NODES * 4 + T - 1) / T;

    // main chain head, uncontended: count(1), scan(2)
    k_count<<<gE8, T>>>(ei);
    k_scan<<<NBLK, SCAN_B>>>();
    cudaEventRecord(eScan, 0);

    // fork: gemm1 + scale on s1, overlapping fill on main
    cudaStreamWaitEvent(s1, eScan, 0);
    k_gemm1<<<gN, T, 0, s1>>>(x, W1);       // (3)
    k_fill<<<gE8, T>>>(ei);                 // (4 <- profiled slot)
    k_scale<<<gN, T, 0, s1>>>();            // (5, s1 after gemm1)
    cudaEventRecord(e1, s1);

    // join: aggregates need hs0 (s1) and CSR (main)
    cudaStreamWaitEvent(0, e1, 0);

    k_agg_update<<<gN4, T>>>(0, 1, b1, W2);
    k_agg_update<<<gN4, T>>>(1, 0, b2, W3);
    k_agg_pool<<<gN4, T>>>(0, b3, batch, ei);
    k_head<<<1, 512>>>(Wlin, blin, out);
}

// round 15
// speedup vs baseline: 1.0436x; 1.0436x over previous
#include <cuda_runtime.h>
#include <cuda_bf16.h>
#include <cuda_fp16.h>
#include <cstdint>

#define N_NODES   100000
#define N_EDGES   3200000
#define N_FEAT    128
#define HIDDEN    16
#define N_CLASSES 10
#define N_GRAPHS  512

#define SCAN_B 1024
#define NBLK   ((N_NODES + SCAN_B - 1) / SCAN_B)   // 98

// ---------------- scratch (static __device__; no allocation) ----------------
__device__ __align__(16)  int    g_csr[N_EDGES];        // src only (4B/edge)
__device__ __align__(16)  int    g_off[N_NODES + 1];
__device__ __align__(16)  int    g_cursor[N_NODES];
__device__ __align__(16)  int    g_cnt[N_NODES];        // self-cleaned by k_scan
__device__ __align__(16)  unsigned long long g_look[NBLK];  // reset by k_head
__device__ __align__(16)  float  g_dinv[N_NODES];
__device__ __align__(128) __half g_hh[2][N_NODES * HIDDEN];  // hs = dinv*h, fp16
__device__ __align__(16)  float  g_pooled[N_GRAPHS * HIDDEN]; // reset by k_head

// ---------------- helpers ----------------
__device__ __forceinline__ void red_add_v4(float4* addr, float4 v) {
    asm volatile("red.global.add.v4.f32 [%0], {%1,%2,%3,%4};"
                 :: "l"(addr), "f"(v.x), "f"(v.y), "f"(v.z), "f"(v.w)
                 : "memory");
}

// int64 iff the high 32-bit words of the first 4 entries are all zero
__device__ __forceinline__ int detect64(const int* __restrict__ ei32) {
    return (ei32[1] | ei32[3] | ei32[5] | ei32[7]) == 0;
}

__device__ __forceinline__ uint2 pack4(float a, float b, float c, float d) {
    __half2 lo = __floats2half2_rn(a, b), hi = __floats2half2_rn(c, d);
    uint2 r;
    r.x = *(unsigned*)&lo; r.y = *(unsigned*)&hi;
    return r;
}

__device__ __forceinline__ float4 unpack4(uint2 u) {
    __half2 lo = *(__half2*)&u.x, hi = *(__half2*)&u.y;
    float2 f0 = __half22float2(lo), f1 = __half22float2(hi);
    return make_float4(f0.x, f0.y, f1.x, f1.y);
}

// load 4 edge indices (src half_off=0 or dst half_off=N_EDGES) at base t*4
__device__ __forceinline__ void load4(const void* p, long long half_off, int t,
                                      int is64, int* v) {
    if (!is64) {
        int4 a = ((const int4*)((const int*)p + half_off))[t];
        v[0] = a.x; v[1] = a.y; v[2] = a.z; v[3] = a.w;
    } else {
        const long long* q = (const long long*)p + half_off;
#pragma unroll
        for (int k = 0; k < 4; k++) v[k] = (int)q[(long long)t * 4 + k];
    }
}

// ---------------- preprocessing ----------------

// in-degree count: plain atomicAdd (no return -> REDG), 4 edges/thread
__global__ void k_count(const void* __restrict__ ei) {
    int is64 = detect64((const int*)ei);
    int t = blockIdx.x * blockDim.x + threadIdx.x;
    if (t * 4 >= N_EDGES) return;
    int dd[4];
    load4(ei, N_EDGES, t, is64, dd);
#pragma unroll
    for (int k = 0; k < 4; k++)
        if ((unsigned)dd[k] >= N_NODES) dd[k] = 0;
#pragma unroll
    for (int k = 0; k < 4; k++)
        atomicAdd(&g_cnt[dd[k]], 1);
}

// single-launch exclusive scan (decoupled lookback) + dinv + cursor init.
// Self-cleans g_cnt for the next replay.
__global__ void k_scan() {
    __shared__ int sh[SCAN_B];
    __shared__ int s_pfx;
    int j = blockIdx.x;
    int i = j * SCAN_B + threadIdx.x;
    int v = (i < N_NODES) ? g_cnt[i] : 0;
    if (i < N_NODES) {
        g_dinv[i] = rsqrtf((float)(v + 1));
        g_cnt[i] = 0;                        // self-clean for next replay
    }
    sh[threadIdx.x] = v;
    __syncthreads();
#pragma unroll
    for (int off = 1; off < SCAN_B; off <<= 1) {
        int t = (threadIdx.x >= off) ? sh[threadIdx.x - off] : 0;
        __syncthreads();
        sh[threadIdx.x] += t;
        __syncthreads();
    }
    unsigned total = (unsigned)sh[SCAN_B - 1];
    if (threadIdx.x == 0)
        atomicExch(&g_look[j], (1ull << 32) | total);   // publish aggregate
    if (threadIdx.x < 32) {
        int lane = threadIdx.x;
        unsigned prefix = 0;
        int k = j - 1;
        if (j == 0 && lane == 0) s_pfx = 0;
        while (k >= 0) {
            int idx = k - lane;
            unsigned st = 1, val = 0;
            if (idx >= 0) {
                unsigned long long w;
                do { w = atomicOr(&g_look[idx], 0ull); st = (unsigned)(w >> 32); }
                while (st == 0);
                val = (unsigned)w;
            }
            unsigned ball = __ballot_sync(0xffffffffu, st == 2 && idx >= 0);
            if (ball) {
                int p = __ffs(ball) - 1;
                unsigned contrib = (lane <= p) ? val : 0;
#pragma unroll
                for (int o = 16; o; o >>= 1)
                    contrib += __shfl_down_sync(0xffffffffu, contrib, o);
                prefix += contrib;
                break;
            } else {
                unsigned contrib = (idx >= 0) ? val : 0;
#pragma unroll
                for (int o = 16; o; o >>= 1)
                    contrib += __shfl_down_sync(0xffffffffu, contrib, o);
                prefix += contrib;
                k -= 32;
            }
        }
        if (lane == 0 && j > 0) {
            atomicExch(&g_look[j], (2ull << 32) | (prefix + total));
            s_pfx = (int)prefix;
        }
        if (lane == 0 && j == 0)
            atomicExch(&g_look[0], (2ull << 32) | total);
    }
    __syncthreads();
    int pfx = s_pfx;
    if (i < N_NODES) {
        int o = sh[threadIdx.x] - v + pfx;   // exclusive + block prefix
        g_off[i] = o;
        g_cursor[i] = o;
    }
    if (i == 0) g_off[N_NODES] = N_EDGES;
}

// scatter src ids into CSR buckets via cursor atomics, 4 edges/thread
__global__ void k_fill(const void* __restrict__ ei) {
    int is64 = detect64((const int*)ei);
    int t = blockIdx.x * blockDim.x + threadIdx.x;
    if (t * 4 >= N_EDGES) return;
    int ss[4], dd[4];
    load4(ei, 0, t, is64, ss);
    load4(ei, N_EDGES, t, is64, dd);
#pragma unroll
    for (int k = 0; k < 4; k++) {
        if ((unsigned)ss[k] >= N_NODES) ss[k] = 0;
        if ((unsigned)dd[k] >= N_NODES) dd[k] = 0;
    }
#pragma unroll
    for (int k = 0; k < 4; k++) {
        int pos = atomicAdd(&g_cursor[dd[k]], 1);
        g_csr[pos] = ss[k];
    }
}

// ---------------- compute ----------------

// hs0 = dinv * (x @ W1), fp16 store. One thread/node. Forked after scan,
// hidden under fill on the side stream.
__global__ void k_gemm1(const float* __restrict__ x, const float* __restrict__ W1) {
    __shared__ float Ws[N_FEAT * HIDDEN];
    for (int i = threadIdx.x; i < N_FEAT * HIDDEN; i += blockDim.x) Ws[i] = W1[i];
    __syncthreads();
    int n = blockIdx.x * blockDim.x + threadIdx.x;
    if (n >= N_NODES) return;
    const float4* xr = (const float4*)(x + (size_t)n * N_FEAT);
    const float4* W4 = (const float4*)Ws;
    float4 a0 = make_float4(0.f, 0.f, 0.f, 0.f), a1 = a0, a2 = a0, a3 = a0;
#pragma unroll 4
    for (int k4 = 0; k4 < N_FEAT / 4; k4++) {
        float4 v = xr[k4];
#pragma unroll
        for (int c = 0; c < 4; c++) {
            float xk = (c == 0) ? v.x : (c == 1) ? v.y : (c == 2) ? v.z : v.w;
            int row = (k4 * 4 + c) * 4;
            float4 w0 = W4[row + 0], w1 = W4[row + 1], w2 = W4[row + 2], w3 = W4[row + 3];
            a0.x += xk * w0.x; a0.y += xk * w0.y; a0.z += xk * w0.z; a0.w += xk * w0.w;
            a1.x += xk * w1.x; a1.y += xk * w1.y; a1.z += xk * w1.z; a1.w += xk * w1.w;
            a2.x += xk * w2.x; a2.y += xk * w2.y; a2.z += xk * w2.z; a2.w += xk * w2.w;
            a3.x += xk * w3.x; a3.y += xk * w3.y; a3.z += xk * w3.z; a3.w += xk * w3.w;
        }
    }
    float di = g_dinv[n];
    uint2 u0 = pack4(di * a0.x, di * a0.y, di * a0.z, di * a0.w);
    uint2 u1 = pack4(di * a1.x, di * a1.y, di * a1.z, di * a1.w);
    uint2 u2 = pack4(di * a2.x, di * a2.y, di * a2.z, di * a2.w);
    uint2 u3 = pack4(di * a3.x, di * a3.y, di * a3.z, di * a3.w);
    uint4* ho = (uint4*)&g_hh[0][n * HIDDEN];
    ho[0] = make_uint4(u0.x, u0.y, u1.x, u1.y);
    ho[1] = make_uint4(u2.x, u2.y, u3.x, u3.y);
}

// sum of hs[src] over the bucket — pure adds, 8-wide batched for MLP
__device__ __forceinline__ float4 agg_edges(const uint2* __restrict__ h4,
                                            int q, int beg, int end, float4 acc) {
    int e = beg;
    for (; e + 8 <= end; e += 8) {
        int s0 = g_csr[e + 0], s1 = g_csr[e + 1], s2 = g_csr[e + 2], s3 = g_csr[e + 3];
        int s4 = g_csr[e + 4], s5 = g_csr[e + 5], s6 = g_csr[e + 6], s7 = g_csr[e + 7];
        uint2 v0 = h4[s0 * 4 + q], v1 = h4[s1 * 4 + q];
        uint2 v2 = h4[s2 * 4 + q], v3 = h4[s3 * 4 + q];
        uint2 v4 = h4[s4 * 4 + q], v5 = h4[s5 * 4 + q];
        uint2 v6 = h4[s6 * 4 + q], v7 = h4[s7 * 4 + q];
#define ACC(vi) { float4 f = unpack4(vi); \
        acc.x += f.x; acc.y += f.y; acc.z += f.z; acc.w += f.w; }
        ACC(v0) ACC(v1) ACC(v2) ACC(v3) ACC(v4) ACC(v5) ACC(v6) ACC(v7)
    }
    for (; e < end; e++) {
        uint2 v = h4[g_csr[e] * 4 + q];
        ACC(v)
    }
#undef ACC
    return acc;
}

// Fused: agg = dinv*(hs[n]+Σhs[src]); t = relu(agg+b); hs_next = dinv*(t@W).
__global__ void k_agg_update(int cur, int nxt, const float* __restrict__ bias,
                             const float* __restrict__ Wn) {
    __shared__ float Ws[HIDDEN * HIDDEN];
    __shared__ float bs[HIDDEN];
    int t = threadIdx.x;
    if (t < HIDDEN * HIDDEN) Ws[t] = Wn[t];
    if (t < HIDDEN) bs[t] = bias[t];
    __syncthreads();
    int idx = blockIdx.x * blockDim.x + t;
    int n = idx >> 2, q = idx & 3;
    if (n >= N_NODES) return;               // whole-warp exit (400000 % 32 == 0)
    const uint2* h4 = (const uint2*)g_hh[cur];
    float4 acc = unpack4(h4[n * 4 + q]);    // self term = hs[n]
    acc = agg_edges(h4, q, g_off[n], g_off[n + 1], acc);
    float di = g_dinv[n];
    int gb = q * 4;
    float t0 = fmaxf(di * acc.x + bs[gb + 0], 0.f);
    float t1 = fmaxf(di * acc.y + bs[gb + 1], 0.f);
    float t2 = fmaxf(di * acc.z + bs[gb + 2], 0.f);
    float t3 = fmaxf(di * acc.w + bs[gb + 3], 0.f);
    float o0 = 0.f, o1 = 0.f, o2 = 0.f, o3 = 0.f;
#pragma unroll
    for (int r = 0; r < 4; r++) {
        float s0 = (r == 0) ? t0 : __shfl_xor_sync(0xffffffffu, t0, r);
        float s1 = (r == 0) ? t1 : __shfl_xor_sync(0xffffffffu, t1, r);
        float s2v = (r == 0) ? t2 : __shfl_xor_sync(0xffffffffu, t2, r);
        float s3 = (r == 0) ? t3 : __shfl_xor_sync(0xffffffffu, t3, r);
        int fb = (q ^ r) * 4;
        o0 += s0 * Ws[(fb + 0) * HIDDEN + gb + 0] + s1 * Ws[(fb + 1) * HIDDEN + gb + 0]
            + s2v * Ws[(fb + 2) * HIDDEN + gb + 0] + s3 * Ws[(fb + 3) * HIDDEN + gb + 0];
        o1 += s0 * Ws[(fb + 0) * HIDDEN + gb + 1] + s1 * Ws[(fb + 1) * HIDDEN + gb + 1]
            + s2v * Ws[(fb + 2) * HIDDEN + gb + 1] + s3 * Ws[(fb + 3) * HIDDEN + gb + 1];
        o2 += s0 * Ws[(fb + 0) * HIDDEN + gb + 2] + s1 * Ws[(fb + 1) * HIDDEN + gb + 2]
            + s2v * Ws[(fb + 2) * HIDDEN + gb + 2] + s3 * Ws[(fb + 3) * HIDDEN + gb + 2];
        o3 += s0 * Ws[(fb + 0) * HIDDEN + gb + 3] + s1 * Ws[(fb + 1) * HIDDEN + gb + 3]
            + s2v * Ws[(fb + 2) * HIDDEN + gb + 3] + s3 * Ws[(fb + 3) * HIDDEN + gb + 3];
    }
    ((uint2*)&g_hh[nxt][n * HIDDEN])[q] = pack4(di * o0, di * o1, di * o2, di * o3);
}

// Fused last layer: agg = dinv*(hs[n]+Σhs[src]) + b3; warp-segmented pool.
__global__ void k_agg_pool(int cur, const float* __restrict__ b3,
                           const void* __restrict__ batch,
                           const void* __restrict__ ei) {
    int is64 = detect64((const int*)ei);    // batch has same dtype as edge_index
    int idx = blockIdx.x * blockDim.x + threadIdx.x;
    int n = idx >> 2, q = idx & 3;
    if (n >= N_NODES) return;               // whole-warp exit
    int lane = threadIdx.x & 31;
    const uint2* h4 = (const uint2*)g_hh[cur];
    float4 acc = unpack4(h4[n * 4 + q]);
    acc = agg_edges(h4, q, g_off[n], g_off[n + 1], acc);
    float di = g_dinv[n];
    float4 bb = ((const float4*)b3)[q];
    acc.x = di * acc.x + bb.x; acc.y = di * acc.y + bb.y;
    acc.z = di * acc.z + bb.z; acc.w = di * acc.w + bb.w;
    int gph = is64 ? (int)((const long long*)batch)[n] : ((const int*)batch)[n];
#pragma unroll
    for (int s = 4; s < 32; s <<= 1) {
        float ox = __shfl_down_sync(0xffffffffu, acc.x, s);
        float oy = __shfl_down_sync(0xffffffffu, acc.y, s);
        float oz = __shfl_down_sync(0xffffffffu, acc.z, s);
        float ow = __shfl_down_sync(0xffffffffu, acc.w, s);
        int   og = __shfl_down_sync(0xffffffffu, gph, s);
        if (lane + s < 32 && og == gph) {
            acc.x += ox; acc.y += oy; acc.z += oz; acc.w += ow;
        }
    }
    int upg = __shfl_up_sync(0xffffffffu, gph, 4);
    bool leader = (lane < 4) || (upg != gph);
    if (leader && (unsigned)gph < N_GRAPHS)
        red_add_v4((float4*)&g_pooled[gph * HIDDEN + q * 4], acc);
}

// out[g][:] = pooled[g] @ Wlin + blin.  ONE 512-thread block (1 graph each).
// Self-cleans g_pooled and g_look for the next replay.
__global__ void k_head(const float* __restrict__ Wlin,
                       const float* __restrict__ blin, float* __restrict__ out) {
    int g = threadIdx.x;                     // 0..511
    float p[HIDDEN];
#pragma unroll
    for (int f = 0; f < HIDDEN; f++) p[f] = g_pooled[g * HIDDEN + f];
#pragma unroll
    for (int c = 0; c < N_CLASSES; c++) {
        float s = blin[c];
#pragma unroll
        for (int f = 0; f < HIDDEN; f++)
            s += p[f] * Wlin[f * N_CLASSES + c];
        out[g * N_CLASSES + c] = s;
    }
#pragma unroll
    for (int f = 0; f < HIDDEN; f++) g_pooled[g * HIDDEN + f] = 0.f;
    if (g < NBLK) g_look[g] = 0ull;
}

// ---------------- launch ----------------
extern "C" void kernel_launch(void* const* d_in, const int* in_sizes, int n_in,
                              void* d_out, int out_size) {
    const float* x     = (const float*)d_in[0];
    const void*  ei    = d_in[1];
    const void*  batch = d_in[2];
    const float* W1    = (const float*)d_in[3];
    const float* b1    = (const float*)d_in[4];
    const float* W2    = (const float*)d_in[5];
    const float* b2    = (const float*)d_in[6];
    const float* W3    = (const float*)d_in[7];
    const float* b3    = (const float*)d_in[8];
    const float* Wlin  = (const float*)d_in[9];
    const float* blin  = (const float*)d_in[10];
    float* out = (float*)d_out;

    static cudaStream_t s1 = nullptr;
    static cudaEvent_t  eScan = nullptr, e1 = nullptr;
    if (!s1) {
        cudaStreamCreateWithFlags(&s1, cudaStreamNonBlocking);
        cudaEventCreateWithFlags(&eScan, cudaEventDisableTiming);
        cudaEventCreateWithFlags(&e1, cudaEventDisableTiming);
    }

    const int T = 256;
    int gN  = (N_NODES + T - 1) / T;
    int gE4 = (N_EDGES / 4 + T - 1) / T;
    int gN4 = (N_NODES * 4 + T - 1) / T;

    // main chain: count(1), scan(2)
    k_count<<<gE4, T>>>(ei);
    k_scan<<<NBLK, SCAN_B>>>();
    cudaEventRecord(eScan, 0);

    // fork: gemm1 (scaled; needs dinv) on s1, hidden under fill on main
    cudaStreamWaitEvent(s1, eScan, 0);
    k_gemm1<<<gN, T, 0, s1>>>(x, W1);       // (3)
    k_fill<<<gE4, T>>>(ei);                 // (4 <- profiled slot)
    cudaEventRecord(e1, s1);

    // join: aggregates need hs0 (s1) and CSR (main)
    cudaStreamWaitEvent(0, e1, 0);

    k_agg_update<<<gN4, T>>>(0, 1, b1, W2);
    k_agg_update<<<gN4, T>>>(1, 0, b2, W3);
    k_agg_pool<<<gN4, T>>>(0, b3, batch, ei);
    k_head<<<1, 512>>>(Wlin, blin, out);
}

// round 16
// speedup vs baseline: 1.0759x; 1.0309x over previous
#include <cuda_runtime.h>
#include <cuda_bf16.h>
#include <cuda_fp16.h>
#include <cstdint>

#define N_NODES   100000
#define N_EDGES   3200000
#define N_FEAT    128
#define HIDDEN    16
#define N_CLASSES 10
#define N_GRAPHS  512

#define SCAN_B 1024
#define NBLK   ((N_NODES + SCAN_B - 1) / SCAN_B)   // 98

// ---------------- scratch (static __device__; no allocation) ----------------
__device__ __align__(16)  int    g_csr[N_EDGES];        // src only (4B/edge)
__device__ __align__(16)  int    g_off[N_NODES + 1];
__device__ __align__(16)  int    g_cursor[N_NODES];
__device__ __align__(16)  int    g_cnt[N_NODES];        // self-cleaned by k_scan
__device__ __align__(16)  unsigned long long g_look[NBLK];  // reset by k_head
__device__ __align__(16)  float  g_dinv[N_NODES];
__device__ __align__(128) __half g_hh[2][N_NODES * HIDDEN];  // hs = dinv*h, fp16
__device__ __align__(16)  float  g_pooled[N_GRAPHS * HIDDEN]; // reset by k_head

// ---------------- helpers ----------------
__device__ __forceinline__ void red_add_v4(float4* addr, float4 v) {
    asm volatile("red.global.add.v4.f32 [%0], {%1,%2,%3,%4};"
                 :: "l"(addr), "f"(v.x), "f"(v.y), "f"(v.z), "f"(v.w)
                 : "memory");
}

// int64 iff the high 32-bit words of the first 4 entries are all zero
__device__ __forceinline__ int detect64(const int* __restrict__ ei32) {
    return (ei32[1] | ei32[3] | ei32[5] | ei32[7]) == 0;
}

__device__ __forceinline__ uint2 pack4(float a, float b, float c, float d) {
    __half2 lo = __floats2half2_rn(a, b), hi = __floats2half2_rn(c, d);
    uint2 r;
    r.x = *(unsigned*)&lo; r.y = *(unsigned*)&hi;
    return r;
}

__device__ __forceinline__ float4 unpack4(uint2 u) {
    __half2 lo = *(__half2*)&u.x, hi = *(__half2*)&u.y;
    float2 f0 = __half22float2(lo), f1 = __half22float2(hi);
    return make_float4(f0.x, f0.y, f1.x, f1.y);
}

// load 4 edge indices (src half_off=0 or dst half_off=N_EDGES) at base t*4
__device__ __forceinline__ void load4(const void* p, long long half_off, int t,
                                      int is64, int* v) {
    if (!is64) {
        int4 a = ((const int4*)((const int*)p + half_off))[t];
        v[0] = a.x; v[1] = a.y; v[2] = a.z; v[3] = a.w;
    } else {
        const long long* q = (const long long*)p + half_off;
#pragma unroll
        for (int k = 0; k < 4; k++) v[k] = (int)q[(long long)t * 4 + k];
    }
}

// ---------------- preprocessing ----------------

// in-degree count: plain atomicAdd (no return -> REDG), 4 edges/thread
__global__ void k_count(const void* __restrict__ ei) {
    int is64 = detect64((const int*)ei);
    int t = blockIdx.x * blockDim.x + threadIdx.x;
    if (t * 4 >= N_EDGES) return;
    int dd[4];
    load4(ei, N_EDGES, t, is64, dd);
#pragma unroll
    for (int k = 0; k < 4; k++)
        if ((unsigned)dd[k] >= N_NODES) dd[k] = 0;
#pragma unroll
    for (int k = 0; k < 4; k++)
        atomicAdd(&g_cnt[dd[k]], 1);
}

// single-launch exclusive scan (decoupled lookback) + dinv + cursor init.
// Self-cleans g_cnt for the next replay.
__global__ void k_scan() {
    __shared__ int sh[SCAN_B];
    __shared__ int s_pfx;
    int j = blockIdx.x;
    int i = j * SCAN_B + threadIdx.x;
    int v = (i < N_NODES) ? g_cnt[i] : 0;
    if (i < N_NODES) {
        g_dinv[i] = rsqrtf((float)(v + 1));
        g_cnt[i] = 0;                        // self-clean for next replay
    }
    sh[threadIdx.x] = v;
    __syncthreads();
#pragma unroll
    for (int off = 1; off < SCAN_B; off <<= 1) {
        int t = (threadIdx.x >= off) ? sh[threadIdx.x - off] : 0;
        __syncthreads();
        sh[threadIdx.x] += t;
        __syncthreads();
    }
    unsigned total = (unsigned)sh[SCAN_B - 1];
    if (threadIdx.x == 0)
        atomicExch(&g_look[j], (1ull << 32) | total);   // publish aggregate
    if (threadIdx.x < 32) {
        int lane = threadIdx.x;
        unsigned prefix = 0;
        int k = j - 1;
        if (j == 0 && lane == 0) s_pfx = 0;
        while (k >= 0) {
            int idx = k - lane;
            unsigned st = 1, val = 0;
            if (idx >= 0) {
                unsigned long long w;
                do { w = atomicOr(&g_look[idx], 0ull); st = (unsigned)(w >> 32); }
                while (st == 0);
                val = (unsigned)w;
            }
            unsigned ball = __ballot_sync(0xffffffffu, st == 2 && idx >= 0);
            if (ball) {
                int p = __ffs(ball) - 1;
                unsigned contrib = (lane <= p) ? val : 0;
#pragma unroll
                for (int o = 16; o; o >>= 1)
                    contrib += __shfl_down_sync(0xffffffffu, contrib, o);
                prefix += contrib;
                break;
            } else {
                unsigned contrib = (idx >= 0) ? val : 0;
#pragma unroll
                for (int o = 16; o; o >>= 1)
                    contrib += __shfl_down_sync(0xffffffffu, contrib, o);
                prefix += contrib;
                k -= 32;
            }
        }
        if (lane == 0 && j > 0) {
            atomicExch(&g_look[j], (2ull << 32) | (prefix + total));
            s_pfx = (int)prefix;
        }
        if (lane == 0 && j == 0)
            atomicExch(&g_look[0], (2ull << 32) | total);
    }
    __syncthreads();
    int pfx = s_pfx;
    if (i < N_NODES) {
        int o = sh[threadIdx.x] - v + pfx;   // exclusive + block prefix
        g_off[i] = o;
        g_cursor[i] = o;
    }
    if (i == 0) g_off[N_NODES] = N_EDGES;
}

// scatter src ids into CSR buckets via cursor atomics, 4 edges/thread
__global__ void k_fill(const void* __restrict__ ei) {
    int is64 = detect64((const int*)ei);
    int t = blockIdx.x * blockDim.x + threadIdx.x;
    if (t * 4 >= N_EDGES) return;
    int ss[4], dd[4];
    load4(ei, 0, t, is64, ss);
    load4(ei, N_EDGES, t, is64, dd);
#pragma unroll
    for (int k = 0; k < 4; k++) {
        if ((unsigned)ss[k] >= N_NODES) ss[k] = 0;
        if ((unsigned)dd[k] >= N_NODES) dd[k] = 0;
    }
#pragma unroll
    for (int k = 0; k < 4; k++) {
        int pos = atomicAdd(&g_cursor[dd[k]], 1);
        g_csr[pos] = ss[k];
    }
}

// ---------------- compute ----------------

// hs0 = dinv * (x @ W1), fp16 store. One thread/node. Forked after scan on a
// LOW-PRIORITY side stream so its blocks yield to the critical-path fill.
__global__ void k_gemm1(const float* __restrict__ x, const float* __restrict__ W1) {
    __shared__ float Ws[N_FEAT * HIDDEN];
    for (int i = threadIdx.x; i < N_FEAT * HIDDEN; i += blockDim.x) Ws[i] = W1[i];
    __syncthreads();
    int n = blockIdx.x * blockDim.x + threadIdx.x;
    if (n >= N_NODES) return;
    const float4* xr = (const float4*)(x + (size_t)n * N_FEAT);
    const float4* W4 = (const float4*)Ws;
    float4 a0 = make_float4(0.f, 0.f, 0.f, 0.f), a1 = a0, a2 = a0, a3 = a0;
#pragma unroll 4
    for (int k4 = 0; k4 < N_FEAT / 4; k4++) {
        float4 v = xr[k4];
#pragma unroll
        for (int c = 0; c < 4; c++) {
            float xk = (c == 0) ? v.x : (c == 1) ? v.y : (c == 2) ? v.z : v.w;
            int row = (k4 * 4 + c) * 4;
            float4 w0 = W4[row + 0], w1 = W4[row + 1], w2 = W4[row + 2], w3 = W4[row + 3];
            a0.x += xk * w0.x; a0.y += xk * w0.y; a0.z += xk * w0.z; a0.w += xk * w0.w;
            a1.x += xk * w1.x; a1.y += xk * w1.y; a1.z += xk * w1.z; a1.w += xk * w1.w;
            a2.x += xk * w2.x; a2.y += xk * w2.y; a2.z += xk * w2.z; a2.w += xk * w2.w;
            a3.x += xk * w3.x; a3.y += xk * w3.y; a3.z += xk * w3.z; a3.w += xk * w3.w;
        }
    }
    float di = g_dinv[n];
    uint2 u0 = pack4(di * a0.x, di * a0.y, di * a0.z, di * a0.w);
    uint2 u1 = pack4(di * a1.x, di * a1.y, di * a1.z, di * a1.w);
    uint2 u2 = pack4(di * a2.x, di * a2.y, di * a2.z, di * a2.w);
    uint2 u3 = pack4(di * a3.x, di * a3.y, di * a3.z, di * a3.w);
    uint4* ho = (uint4*)&g_hh[0][n * HIDDEN];
    ho[0] = make_uint4(u0.x, u0.y, u1.x, u1.y);
    ho[1] = make_uint4(u2.x, u2.y, u3.x, u3.y);
}

// sum of hs[src] over the bucket — pure adds, 8-wide batched for MLP
__device__ __forceinline__ float4 agg_edges(const uint2* __restrict__ h4,
                                            int q, int beg, int end, float4 acc) {
    int e = beg;
    for (; e + 8 <= end; e += 8) {
        int s0 = g_csr[e + 0], s1 = g_csr[e + 1], s2 = g_csr[e + 2], s3 = g_csr[e + 3];
        int s4 = g_csr[e + 4], s5 = g_csr[e + 5], s6 = g_csr[e + 6], s7 = g_csr[e + 7];
        uint2 v0 = h4[s0 * 4 + q], v1 = h4[s1 * 4 + q];
        uint2 v2 = h4[s2 * 4 + q], v3 = h4[s3 * 4 + q];
        uint2 v4 = h4[s4 * 4 + q], v5 = h4[s5 * 4 + q];
        uint2 v6 = h4[s6 * 4 + q], v7 = h4[s7 * 4 + q];
#define ACC(vi) { float4 f = unpack4(vi); \
        acc.x += f.x; acc.y += f.y; acc.z += f.z; acc.w += f.w; }
        ACC(v0) ACC(v1) ACC(v2) ACC(v3) ACC(v4) ACC(v5) ACC(v6) ACC(v7)
    }
    for (; e < end; e++) {
        uint2 v = h4[g_csr[e] * 4 + q];
        ACC(v)
    }
#undef ACC
    return acc;
}

// Fused: agg = dinv*(hs[n]+Σhs[src]); t = relu(agg+b); hs_next = dinv*(t@W).
// PDL: smem prologue runs during producer drain; griddepsync before CSR/h reads.
__global__ void k_agg_update(int cur, int nxt, const float* __restrict__ bias,
                             const float* __restrict__ Wn) {
    __shared__ float Ws[HIDDEN * HIDDEN];
    __shared__ float bs[HIDDEN];
    int t = threadIdx.x;
    if (t < HIDDEN * HIDDEN) Ws[t] = Wn[t];   // inputs: safe pre-sync
    if (t < HIDDEN) bs[t] = bias[t];
    __syncthreads();
    cudaGridDependencySynchronize();          // wait for producer data
    int idx = blockIdx.x * blockDim.x + t;
    int n = idx >> 2, q = idx & 3;
    if (n >= N_NODES) return;               // whole-warp exit (400000 % 32 == 0)
    const uint2* h4 = (const uint2*)g_hh[cur];
    float4 acc = unpack4(h4[n * 4 + q]);    // self term = hs[n]
    acc = agg_edges(h4, q, g_off[n], g_off[n + 1], acc);
    float di = g_dinv[n];
    int gb = q * 4;
    float t0 = fmaxf(di * acc.x + bs[gb + 0], 0.f);
    float t1 = fmaxf(di * acc.y + bs[gb + 1], 0.f);
    float t2 = fmaxf(di * acc.z + bs[gb + 2], 0.f);
    float t3 = fmaxf(di * acc.w + bs[gb + 3], 0.f);
    float o0 = 0.f, o1 = 0.f, o2 = 0.f, o3 = 0.f;
#pragma unroll
    for (int r = 0; r < 4; r++) {
        float s0 = (r == 0) ? t0 : __shfl_xor_sync(0xffffffffu, t0, r);
        float s1 = (r == 0) ? t1 : __shfl_xor_sync(0xffffffffu, t1, r);
        float s2v = (r == 0) ? t2 : __shfl_xor_sync(0xffffffffu, t2, r);
        float s3 = (r == 0) ? t3 : __shfl_xor_sync(0xffffffffu, t3, r);
        int fb = (q ^ r) * 4;
        o0 += s0 * Ws[(fb + 0) * HIDDEN + gb + 0] + s1 * Ws[(fb + 1) * HIDDEN + gb + 0]
            + s2v * Ws[(fb + 2) * HIDDEN + gb + 0] + s3 * Ws[(fb + 3) * HIDDEN + gb + 0];
        o1 += s0 * Ws[(fb + 0) * HIDDEN + gb + 1] + s1 * Ws[(fb + 1) * HIDDEN + gb + 1]
            + s2v * Ws[(fb + 2) * HIDDEN + gb + 1] + s3 * Ws[(fb + 3) * HIDDEN + gb + 1];
        o2 += s0 * Ws[(fb + 0) * HIDDEN + gb + 2] + s1 * Ws[(fb + 1) * HIDDEN + gb + 2]
            + s2v * Ws[(fb + 2) * HIDDEN + gb + 2] + s3 * Ws[(fb + 3) * HIDDEN + gb + 2];
        o3 += s0 * Ws[(fb + 0) * HIDDEN + gb + 3] + s1 * Ws[(fb + 1) * HIDDEN + gb + 3]
            + s2v * Ws[(fb + 2) * HIDDEN + gb + 3] + s3 * Ws[(fb + 3) * HIDDEN + gb + 3];
    }
    ((uint2*)&g_hh[nxt][n * HIDDEN])[q] = pack4(di * o0, di * o1, di * o2, di * o3);
}

// Fused last layer: agg = dinv*(hs[n]+Σhs[src]) + b3; warp-segmented pool. PDL.
__global__ void k_agg_pool(int cur, const float* __restrict__ b3,
                           const void* __restrict__ batch,
                           const void* __restrict__ ei) {
    int is64 = detect64((const int*)ei);    // inputs: safe pre-sync
    int idx = blockIdx.x * blockDim.x + threadIdx.x;
    int n = idx >> 2, q = idx & 3;
    float4 bb = (n < N_NODES) ? ((const float4*)b3)[q] : make_float4(0,0,0,0);
    int gph = 0;
    if (n < N_NODES)
        gph = is64 ? (int)((const long long*)batch)[n] : ((const int*)batch)[n];
    cudaGridDependencySynchronize();          // wait for agg2's hs
    if (n >= N_NODES) return;               // whole-warp exit
    int lane = threadIdx.x & 31;
    const uint2* h4 = (const uint2*)g_hh[cur];
    float4 acc = unpack4(h4[n * 4 + q]);
    acc = agg_edges(h4, q, g_off[n], g_off[n + 1], acc);
    float di = g_dinv[n];
    acc.x = di * acc.x + bb.x; acc.y = di * acc.y + bb.y;
    acc.z = di * acc.z + bb.z; acc.w = di * acc.w + bb.w;
#pragma unroll
    for (int s = 4; s < 32; s <<= 1) {
        float ox = __shfl_down_sync(0xffffffffu, acc.x, s);
        float oy = __shfl_down_sync(0xffffffffu, acc.y, s);
        float oz = __shfl_down_sync(0xffffffffu, acc.z, s);
        float ow = __shfl_down_sync(0xffffffffu, acc.w, s);
        int   og = __shfl_down_sync(0xffffffffu, gph, s);
        if (lane + s < 32 && og == gph) {
            acc.x += ox; acc.y += oy; acc.z += oz; acc.w += ow;
        }
    }
    int upg = __shfl_up_sync(0xffffffffu, gph, 4);
    bool leader = (lane < 4) || (upg != gph);
    if (leader && (unsigned)gph < N_GRAPHS)
        red_add_v4((float4*)&g_pooled[gph * HIDDEN + q * 4], acc);
}

// out[g][:] = pooled[g] @ Wlin + blin.  ONE 512-thread block. PDL.
// Self-cleans g_pooled and g_look for the next replay.
__global__ void k_head(const float* __restrict__ Wlin,
                       const float* __restrict__ blin, float* __restrict__ out) {
    int g = threadIdx.x;                     // 0..511
    __shared__ float Wl[HIDDEN * N_CLASSES];
    __shared__ float bl[N_CLASSES];
    if (g < HIDDEN * N_CLASSES) Wl[g] = Wlin[g];   // inputs: safe pre-sync
    if (g < N_CLASSES) bl[g] = blin[g];
    __syncthreads();
    cudaGridDependencySynchronize();          // wait for pooled sums
    float p[HIDDEN];
#pragma unroll
    for (int f = 0; f < HIDDEN; f++) p[f] = g_pooled[g * HIDDEN + f];
#pragma unroll
    for (int c = 0; c < N_CLASSES; c++) {
        float s = bl[c];
#pragma unroll
        for (int f = 0; f < HIDDEN; f++)
            s += p[f] * Wl[f * N_CLASSES + c];
        out[g * N_CLASSES + c] = s;
    }
#pragma unroll
    for (int f = 0; f < HIDDEN; f++) g_pooled[g * HIDDEN + f] = 0.f;
    if (g < NBLK) g_look[g] = 0ull;
}

// ---------------- launch ----------------
extern "C" void kernel_launch(void* const* d_in, const int* in_sizes, int n_in,
                              void* d_out, int out_size) {
    const float* x     = (const float*)d_in[0];
    const void*  ei    = d_in[1];
    const void*  batch = d_in[2];
    const float* W1    = (const float*)d_in[3];
    const float* b1    = (const float*)d_in[4];
    const float* W2    = (const float*)d_in[5];
    const float* b2    = (const float*)d_in[6];
    const float* W3    = (const float*)d_in[7];
    const float* b3    = (const float*)d_in[8];
    const float* Wlin  = (const float*)d_in[9];
    const float* blin  = (const float*)d_in[10];
    float* out = (float*)d_out;

    static cudaStream_t s1 = nullptr;
    static cudaEvent_t  eScan = nullptr, e1 = nullptr;
    if (!s1) {
        int lo, hi;
        cudaDeviceGetStreamPriorityRange(&lo, &hi);
        cudaStreamCreateWithPriority(&s1, cudaStreamNonBlocking, lo); // LOW prio
        cudaEventCreateWithFlags(&eScan, cudaEventDisableTiming);
        cudaEventCreateWithFlags(&e1, cudaEventDisableTiming);
    }

    const int T = 256;
    int gN  = (N_NODES + T - 1) / T;
    int gE4 = (N_EDGES / 4 + T - 1) / T;
    int gN4 = (N_NODES * 4 + T - 1) / T;

    // main chain: count(1), scan(2)
    k_count<<<gE4, T>>>(ei);
    k_scan<<<NBLK, SCAN_B>>>();
    cudaEventRecord(eScan, 0);

    // fork: gemm1 (scaled; needs dinv) on low-prio s1, hidden under fill
    cudaStreamWaitEvent(s1, eScan, 0);
    k_gemm1<<<gN, T, 0, s1>>>(x, W1);       // (3)
    k_fill<<<gE4, T>>>(ei);                 // (4 <- profiled slot)
    cudaEventRecord(e1, s1);

    // join: aggregates need hs0 (s1) and CSR (main)
    cudaStreamWaitEvent(0, e1, 0);

    // PDL chain: each consumer launches early, preloads smem, then griddepsync
    cudaLaunchAttribute pdlAttr[1];
    pdlAttr[0].id = cudaLaunchAttributeProgrammaticStreamSerialization;
    pdlAttr[0].val.programmaticStreamSerializationAllowed = 1;

    cudaLaunchConfig_t cfg = {};
    cfg.blockDim = {(unsigned)T, 1, 1};
    cfg.stream = 0;
    cfg.attrs = pdlAttr;
    cfg.numAttrs = 1;

    cfg.gridDim = {(unsigned)gN4, 1, 1};
    cudaLaunchKernelEx(&cfg, k_agg_update, 0, 1, (const float*)b1, (const float*)W2);
    cudaLaunchKernelEx(&cfg, k_agg_update, 1, 0, (const float*)b2, (const float*)W3);
    cudaLaunchKernelEx(&cfg, k_agg_pool, 0, (const float*)b3, (const void*)batch,
                       (const void*)ei);

    cfg.gridDim = {1, 1, 1};
    cfg.blockDim = {512, 1, 1};
    cudaLaunchKernelEx(&cfg, k_head, (const float*)Wlin, (const float*)blin,
                       (float*)out);
}